// round 5
// baseline (speedup 1.0000x reference)
#include <cuda_runtime.h>
#include <cstddef>

// HealEncoding: out[b, f*NLVL + l] = sum_{n<4} params[l, neigh_pix[l,n,b], f] * neigh_weight[l,n,b]
// params: (8,196608,8) f32; neigh_pix: (8,4,1M) i32; neigh_weight: (8,4,1M) f32; out: (1M,64) f32

#define NLVL   8
#define FDIM   8
#define NPIX   196608
#define BATCH  1000000
#define BBLK   32                 // batch elements per barrier-iteration
#define NTILES (BATCH / BBLK)     // 31250
#define BPSM   5
#define GRID   (148 * BPSM)       // 740: exact multiple of SM count -> no tail wave

// Levels 0-3 tables: 12+48+192+768 = 1020 pixels * 32B = 32.6KB in SMEM.
#define TAB_F4 2040
__device__ __constant__ int c_tab_base[4] = {0, 24, 120, 504};   // float4 offsets

// Block (32,8): warp == one level. Pair-cooperative gather (lanes 2j,2j+1 split
// the 32B feature row; h = lane&1 picks the 16B half): 1 L1 wavefront/pixel for
// global levels. Levels 0-3 gather from SMEM (crossbar doesn't pay the 128B-line
// wavefront tax for random 16B accesses). Persistent blocks amortize the table.
__global__ void __launch_bounds__(256, BPSM)
heal_encoding_kernel(const float* __restrict__ params,
                     const int*   __restrict__ neigh_pix,
                     const float* __restrict__ neigh_weight,
                     float*       __restrict__ out)
{
    __shared__ float4 s_tab[TAB_F4];       // lvl0-3 param tables
    __shared__ float  s[64 * 33];          // staging: [col c][b_local], stride 33 conflict-free

    const int lane = threadIdx.x;
    const int lvl  = threadIdx.y;          // warp == level
    const int j    = lane >> 1;            // batch element within 16-subtile
    const int h    = lane & 1;             // 16B half of the 32B feature row
    const int tid  = lvl * 32 + lane;

    // One-time cooperative table load (levels 0-3), coalesced float4 copies.
    {
        const float4* __restrict__ g4 = reinterpret_cast<const float4*>(params);
        for (int i = tid; i < 24;   i += 256) s_tab[0   + i] = __ldg(&g4[0 * (NPIX*2) + i]);
        for (int i = tid; i < 96;   i += 256) s_tab[24  + i] = __ldg(&g4[1 * (NPIX*2) + i]);
        for (int i = tid; i < 384;  i += 256) s_tab[120 + i] = __ldg(&g4[2 * (NPIX*2) + i]);
        for (int i = tid; i < 1536; i += 256) s_tab[504 + i] = __ldg(&g4[3 * (NPIX*2) + i]);
    }
    __syncthreads();

    const bool use_lds  = (lvl < 4);
    const int  tab_base = use_lds ? c_tab_base[lvl] : 0;
    const float4* __restrict__ p4 =
        reinterpret_cast<const float4*>(params) + (size_t)lvl * (NPIX * 2);

    for (int t = blockIdx.x; t < NTILES; t += GRID) {
        // Two 16-element subtiles per barrier pair.
#pragma unroll
        for (int s2 = 0; s2 < 2; s2++) {
            const int b  = t * BBLK + s2 * 16 + j;
            const int j2 = s2 * 16 + j;

            int   pix[4];
            float w[4];
#pragma unroll
            for (int n = 0; n < 4; n++) {
                const size_t off = (size_t)(lvl * 4 + n) * BATCH + b;
                pix[n] = __ldg(&neigh_pix[off]);
                w[n]   = __ldg(&neigh_weight[off]);
            }

            float4 g[4];
            if (use_lds) {
#pragma unroll
                for (int n = 0; n < 4; n++)
                    g[n] = s_tab[tab_base + pix[n] * 2 + h];
            } else {
#pragma unroll
                for (int n = 0; n < 4; n++)
                    g[n] = __ldg(&p4[(size_t)pix[n] * 2 + h]);
            }

            float4 a = make_float4(0.f, 0.f, 0.f, 0.f);
#pragma unroll
            for (int n = 0; n < 4; n++) {
                a.x = fmaf(w[n], g[n].x, a.x);
                a.y = fmaf(w[n], g[n].y, a.y);
                a.z = fmaf(w[n], g[n].z, a.z);
                a.w = fmaf(w[n], g[n].w, a.w);
            }

            // This thread owns features f = 4h..4h+3; out column c = f*8 + lvl.
            // Store banks (c fixed, j2 varies): (c + j2) % 32 distinct -> clean.
#pragma unroll
            for (int k = 0; k < 4; k++) {
                const int c = (h * 4 + k) * NLVL + lvl;
                const float v = (k == 0) ? a.x : (k == 1) ? a.y : (k == 2) ? a.z : a.w;
                s[c * 33 + j2] = v;
            }
        }

        __syncthreads();

        // Coalesced write-out: 32 b x 64 cols = 2048 floats, 256 threads, 8 iters.
        // Read banks (bl fixed, c varies): (c + bl) % 32 distinct -> clean.
        float* __restrict__ outp = out + (size_t)t * BBLK * 64;
#pragma unroll
        for (int i = 0; i < 8; i++) {
            const int e  = i * 256 + tid;
            const int bl = e >> 6;
            const int c  = e & 63;
            outp[e] = s[c * 33 + bl];
        }

        __syncthreads();   // staging tile reused next iteration
    }
}

extern "C" void kernel_launch(void* const* d_in, const int* in_sizes, int n_in,
                              void* d_out, int out_size)
{
    const float* params       = (const float*)d_in[0];
    const int*   neigh_pix    = (const int*)d_in[1];
    const float* neigh_weight = (const float*)d_in[2];
    float*       out          = (float*)d_out;

    dim3 block(32, 8);
    heal_encoding_kernel<<<GRID, block>>>(params, neigh_pix, neigh_weight, out);
}

// round 6
// speedup vs baseline: 1.5432x; 1.5432x over previous
#include <cuda_runtime.h>
#include <cstddef>

// HealEncoding: out[b, f*NLVL + l] = sum_{n<4} params[l, neigh_pix[l,n,b], f] * neigh_weight[l,n,b]
// params: (8,196608,8) f32; neigh_pix: (8,4,1M) i32; neigh_weight: (8,4,1M) f32; out: (1M,64) f32

#define NLVL  8
#define FDIM  8
#define NPIX  196608
#define BATCH 1000000
#define BBLK  32          // batch elements per block

// Block (32,16): 16 warps = 2 half-tiles x 8 levels. Per-warp work identical to
// the R3 winner (pair-cooperative gather: lanes 2j,2j+1 split the 32B feature
// row, h = lane&1 -> 16B half, 1 L1 wavefront per random pixel). Changes vs R3:
//  - 32 b per block -> half the blocks, half the barriers per element
//  - __ldcs on idx/weights + __stcs on out: streaming evict-first, keeps the
//    ~8MB gather table resident in L2 against 512MB of read-once traffic
__global__ void __launch_bounds__(512, 4)
heal_encoding_kernel(const float* __restrict__ params,
                     const int*   __restrict__ neigh_pix,
                     const float* __restrict__ neigh_weight,
                     float*       __restrict__ out)
{
    __shared__ float s[64 * 33];   // [out-column c][b_local j2], stride 33 conflict-free

    const int lane = threadIdx.x;
    const int y    = threadIdx.y;          // 0..15
    const int lvl  = y & 7;                // warp's level
    const int half = y >> 3;               // which 16-element half of the tile
    const int j    = lane >> 1;            // batch element within half [0,16)
    const int h    = lane & 1;             // 16B half of the 32B feature row
    const int j2   = half * 16 + j;        // b_local [0,32)
    const int b    = blockIdx.x * BBLK + j2;

    const float4* __restrict__ p4 =
        reinterpret_cast<const float4*>(params) + (size_t)lvl * (NPIX * 2);

    // Coalesced idx/weight loads (pair lanes broadcast the same address).
    int   pix[4];
    float w[4];
#pragma unroll
    for (int n = 0; n < 4; n++) {
        const size_t off = (size_t)(lvl * 4 + n) * BATCH + b;
        pix[n] = __ldcs(&neigh_pix[off]);
        w[n]   = __ldcs(&neigh_weight[off]);
    }

    // 4 gathers: one LDG.128 per warp covers 16 pixels (2 lanes per 32B row).
    float4 g[4];
#pragma unroll
    for (int n = 0; n < 4; n++) {
        g[n] = __ldg(&p4[(size_t)pix[n] * 2 + h]);
    }

    float4 a = make_float4(0.f, 0.f, 0.f, 0.f);
#pragma unroll
    for (int n = 0; n < 4; n++) {
        a.x = fmaf(w[n], g[n].x, a.x);
        a.y = fmaf(w[n], g[n].y, a.y);
        a.z = fmaf(w[n], g[n].z, a.z);
        a.w = fmaf(w[n], g[n].w, a.w);
    }

    // Stage: this thread owns features f = 4h..4h+3; out column c = f*8 + lvl.
    // Store banks: (c*33 + j2) % 32 = (c + j2) % 32; within the warp c depends
    // on h and j2 on j such that banks = const + (2j + h) = const + lane -> clean.
#pragma unroll
    for (int k = 0; k < 4; k++) {
        const int c = (h * 4 + k) * NLVL + lvl;
        const float v = (k == 0) ? a.x : (k == 1) ? a.y : (k == 2) ? a.z : a.w;
        s[c * 33 + j2] = v;
    }

    __syncthreads();

    // Coalesced write-out: 32 b x 64 cols = 2048 floats, 512 threads, 4 iters.
    // Read banks: (c + bl) % 32 distinct across the warp -> clean.
    const int tid = y * 32 + lane;
    float* __restrict__ outp = out + (size_t)blockIdx.x * BBLK * 64;
#pragma unroll
    for (int i = 0; i < 4; i++) {
        const int e  = i * 512 + tid;
        const int bl = e >> 6;
        const int c  = e & 63;
        __stcs(&outp[e], s[c * 33 + bl]);
    }
}

extern "C" void kernel_launch(void* const* d_in, const int* in_sizes, int n_in,
                              void* d_out, int out_size)
{
    const float* params       = (const float*)d_in[0];
    const int*   neigh_pix    = (const int*)d_in[1];
    const float* neigh_weight = (const float*)d_in[2];
    float*       out          = (float*)d_out;

    dim3 block(32, 16);
    dim3 grid(BATCH / BBLK);   // 31,250
    heal_encoding_kernel<<<grid, block>>>(params, neigh_pix, neigh_weight, out);
}

// round 7
// speedup vs baseline: 1.6909x; 1.0957x over previous
#include <cuda_runtime.h>
#include <cstddef>

// HealEncoding: out[b, f*NLVL + l] = sum_{n<4} params[l, neigh_pix[l,n,b], f] * neigh_weight[l,n,b]
// params: (8,196608,8) f32; neigh_pix: (8,4,1M) i32; neigh_weight: (8,4,1M) f32; out: (1M,64) f32

#define NLVL  8
#define FDIM  8
#define NPIX  196608
#define BATCH 1000000
#define BBLK  32          // batch elements per block (2 per thread)

// Block (32,8): warp == one level. Pair-cooperative gather (lanes 2j,2j+1 split
// the 32B feature row of a pixel; h = lane&1 -> 16B half): 1 L1 wavefront per
// random pixel. vs the 147.5us version:
//  - each thread handles elements 2j and 2j+1 -> idx/weights load as int2/float2
//    spanning a full 128B line per warp (halves idx/w wavefronts)
//  - staging swizzle c*33 + (c>>5) + j2 fixes a latent 2-way STS bank conflict
//    (store bank = const + 2j + h = const + lane -> all distinct)
//  - one barrier per 32 elements instead of per 16
__global__ void __launch_bounds__(256, 6)
heal_encoding_kernel(const float* __restrict__ params,
                     const int*   __restrict__ neigh_pix,
                     const float* __restrict__ neigh_weight,
                     float*       __restrict__ out)
{
    __shared__ float s[64 * 33];   // max addr = 63*33 + 1 + 31 = 2111 < 2112

    const int lane = threadIdx.x;
    const int lvl  = threadIdx.y;          // warp == level
    const int j    = lane >> 1;            // pixel-slot within warp [0,16)
    const int h    = lane & 1;             // 16B half of the 32B feature row
    const int b0   = blockIdx.x * BBLK;    // even

    const float4* __restrict__ p4 =
        reinterpret_cast<const float4*>(params) + (size_t)lvl * (NPIX * 2);

    // Vectorized idx/weight loads: int2/float2 at element pair (2j, 2j+1).
    // Pair lanes broadcast the same address; warp spans 16*8B = 128B = 1 wf.
    int2   pix2[4];
    float2 w2[4];
#pragma unroll
    for (int n = 0; n < 4; n++) {
        const size_t off = (size_t)(lvl * 4 + n) * BATCH + b0;   // even
        pix2[n] = __ldg(reinterpret_cast<const int2*>(neigh_pix + off) + j);
        w2[n]   = __ldg(reinterpret_cast<const float2*>(neigh_weight + off) + j);
    }

#pragma unroll
    for (int s2 = 0; s2 < 2; s2++) {
        // 4 gathers: one LDG.128 per warp covers 16 random pixels.
        float4 g[4];
#pragma unroll
        for (int n = 0; n < 4; n++) {
            const int pix = (s2 == 0) ? pix2[n].x : pix2[n].y;
            g[n] = __ldg(&p4[(size_t)pix * 2 + h]);
        }

        float4 a = make_float4(0.f, 0.f, 0.f, 0.f);
#pragma unroll
        for (int n = 0; n < 4; n++) {
            const float wn = (s2 == 0) ? w2[n].x : w2[n].y;
            a.x = fmaf(wn, g[n].x, a.x);
            a.y = fmaf(wn, g[n].y, a.y);
            a.z = fmaf(wn, g[n].z, a.z);
            a.w = fmaf(wn, g[n].w, a.w);
        }

        // Stage: this thread owns features f = 4h..4h+3 of element j2 = 2j+s2;
        // out column c = f*8 + lvl = 32h + 8k + lvl.
        // addr = c*33 + (c>>5) + j2 -> store bank = (8k+lvl+s2 + 2j+h) % 32,
        // i.e. const + lane: conflict-free.
        const int j2 = 2 * j + s2;
#pragma unroll
        for (int k = 0; k < 4; k++) {
            const int c = (h * 4 + k) * NLVL + lvl;
            const float v = (k == 0) ? a.x : (k == 1) ? a.y : (k == 2) ? a.z : a.w;
            s[c * 33 + (c >> 5) + j2] = v;
        }
    }

    __syncthreads();

    // Coalesced write-out: 32 b x 64 cols = 2048 floats, 256 threads, 8 iters.
    // Within a warp bl is fixed and c spans 32 consecutive values with constant
    // (c>>5): bank = (c + bl + const) % 32 all distinct: conflict-free.
    const int tid = lvl * 32 + lane;
    float* __restrict__ outp = out + (size_t)b0 * 64;
#pragma unroll
    for (int i = 0; i < 8; i++) {
        const int e  = i * 256 + tid;
        const int bl = e >> 6;
        const int c  = e & 63;
        outp[e] = s[c * 33 + (c >> 5) + bl];
    }
}

extern "C" void kernel_launch(void* const* d_in, const int* in_sizes, int n_in,
                              void* d_out, int out_size)
{
    const float* params       = (const float*)d_in[0];
    const int*   neigh_pix    = (const int*)d_in[1];
    const float* neigh_weight = (const float*)d_in[2];
    float*       out          = (float*)d_out;

    dim3 block(32, 8);
    dim3 grid(BATCH / BBLK);   // 31,250
    heal_encoding_kernel<<<grid, block>>>(params, neigh_pix, neigh_weight, out);
}

// round 8
// speedup vs baseline: 1.7400x; 1.0290x over previous
#include <cuda_runtime.h>
#include <cstddef>

// HealEncoding: out[b, f*NLVL + l] = sum_{n<4} params[l, neigh_pix[l,n,b], f] * neigh_weight[l,n,b]
// params: (8,196608,8) f32; neigh_pix: (8,4,1M) i32; neigh_weight: (8,4,1M) f32; out: (1M,64) f32

#define NLVL  8
#define FDIM  8
#define NPIX  196608
#define BATCH 1000000
#define BBLK  32          // batch elements per block (2 per thread)

// Block (32,8): warp == one level. Pair-cooperative gather (lanes 2j,2j+1 split
// the 32B feature row; h = lane&1 -> 16B half): 1 L1 wavefront per random pixel.
// vs R7 (141.8us): force 8 blocks/SM (regs<=32) to restore the occupancy that
// R7 gave up (71% -> ~90%), since L1 util (85%) is the remaining gap to the
// wavefront floor. Neighbor loop split 2+2 and all indexing int32 so 32 regs
// fits without local spills.
__global__ void __launch_bounds__(256, 8)
heal_encoding_kernel(const float* __restrict__ params,
                     const int*   __restrict__ neigh_pix,
                     const float* __restrict__ neigh_weight,
                     float*       __restrict__ out)
{
    __shared__ float s[64 * 33];   // staging; max addr 63*33+1+31 = 2111

    const int lane = threadIdx.x;
    const int lvl  = threadIdx.y;          // warp == level
    const int j    = lane >> 1;            // pixel-slot within warp [0,16)
    const int h    = lane & 1;             // 16B half of the 32B feature row
    const int b0   = blockIdx.x * BBLK;    // even

    const float4* __restrict__ p4 =
        reinterpret_cast<const float4*>(params) + lvl * (NPIX * 2);

    // Vectorized idx/weight loads: int2/float2 covering elements (2j, 2j+1).
    // Warp spans 16*8B = 128B = 1 wavefront per load. All-int32 offsets.
    int2   pix2[4];
    float2 w2[4];
#pragma unroll
    for (int n = 0; n < 4; n++) {
        const int off = (lvl * 4 + n) * BATCH + b0;   // < 32M, fits int32
        pix2[n] = __ldg(reinterpret_cast<const int2*>(neigh_pix + off) + j);
        w2[n]   = __ldg(reinterpret_cast<const float2*>(neigh_weight + off) + j);
    }

#pragma unroll
    for (int s2 = 0; s2 < 2; s2++) {
        float4 a = make_float4(0.f, 0.f, 0.f, 0.f);

        // Neighbors in two pairs: g[2] live at a time (reg pressure), still
        // 2 outstanding gathers per thread x 64 warps/SM for latency hiding.
#pragma unroll
        for (int np = 0; np < 2; np++) {
            float4 g0, g1;
            {
                const int pa = (s2 == 0) ? pix2[2*np+0].x : pix2[2*np+0].y;
                const int pb = (s2 == 0) ? pix2[2*np+1].x : pix2[2*np+1].y;
                g0 = __ldg(&p4[pa * 2 + h]);
                g1 = __ldg(&p4[pb * 2 + h]);
            }
            const float wa = (s2 == 0) ? w2[2*np+0].x : w2[2*np+0].y;
            const float wb = (s2 == 0) ? w2[2*np+1].x : w2[2*np+1].y;
            a.x = fmaf(wa, g0.x, a.x);  a.x = fmaf(wb, g1.x, a.x);
            a.y = fmaf(wa, g0.y, a.y);  a.y = fmaf(wb, g1.y, a.y);
            a.z = fmaf(wa, g0.z, a.z);  a.z = fmaf(wb, g1.z, a.z);
            a.w = fmaf(wa, g0.w, a.w);  a.w = fmaf(wb, g1.w, a.w);
        }

        // Stage element j2 = 2j+s2; out column c = (4h+k)*8 + lvl.
        // addr = c*33 + (c>>5) + j2 -> bank = const + 2j + h = const + lane:
        // conflict-free.
        const int j2 = 2 * j + s2;
#pragma unroll
        for (int k = 0; k < 4; k++) {
            const int c = (h * 4 + k) * NLVL + lvl;
            const float v = (k == 0) ? a.x : (k == 1) ? a.y : (k == 2) ? a.z : a.w;
            s[c * 33 + (c >> 5) + j2] = v;
        }
    }

    __syncthreads();

    // Coalesced write-out: 32 b x 64 cols = 2048 floats, 8 iters.
    // Read bank = (c + bl + const) % 32 distinct across warp: conflict-free.
    const int tid = lvl * 32 + lane;
    float* __restrict__ outp = out + (size_t)b0 * 64;
#pragma unroll
    for (int i = 0; i < 8; i++) {
        const int e  = i * 256 + tid;
        const int bl = e >> 6;
        const int c  = e & 63;
        outp[e] = s[c * 33 + (c >> 5) + bl];
    }
}

extern "C" void kernel_launch(void* const* d_in, const int* in_sizes, int n_in,
                              void* d_out, int out_size)
{
    const float* params       = (const float*)d_in[0];
    const int*   neigh_pix    = (const int*)d_in[1];
    const float* neigh_weight = (const float*)d_in[2];
    float*       out          = (float*)d_out;

    dim3 block(32, 8);
    dim3 grid(BATCH / BBLK);   // 31,250
    heal_encoding_kernel<<<grid, block>>>(params, neigh_pix, neigh_weight, out);
}